// round 16
// baseline (speedup 1.0000x reference)
#include <cuda_runtime.h>
#include <cstdint>

// ---------------- Problem constants ----------------
#define B_   4
#define N_   6
#define D_   41
#define FH_  16
#define FW_  44
#define C_   64
#define NX0_ 200
#define NX1_ 200
#define NPTS (B_ * N_ * D_ * FH_ * FW_)        // 692736
#define SCRATCH_ELEMS ((size_t)B_ * NX0_ * NX1_ * C_)  // 10,240,000 floats (~41MB)
#define ZERO_BLOCKS 1250                       // 1,280,000 v8-stores / (256*4)

// frustum steps (fp32 compile-time, identical to jnp.linspace's step)
#define XSTEP (703.0f / 43.0f)
#define YSTEP 17.0f

// scratch accumulator: [B, X, Y, C] channel-contiguous.
// Zeroed by the prep kernel's STG.256 sweep immediately before the splat.
// The kernel-store sweep is load-bearing: it leaves scratch L2-resident, and
// warm-line atomics are ~3x faster than cold (confirmed unconfounded in R6).
__device__ float g_scratch[SCRATCH_ELEMS];

// per-(b,n) params: 24 floats = { Pinv[9], M[9] (=rots@inv(K)), post_trans[3], trans[3] }
__device__ float g_par[B_ * N_ * 24];

// 3-term dot, XLA-fusion style: separate mul + LTR add, NO fma. (Bit-matches ref.)
__device__ __forceinline__ float dot3_nofma(float a0, float b0, float a1, float b1,
                                            float a2, float b2) {
    return __fadd_rn(__fadd_rn(__fmul_rn(a0, b0), __fmul_rn(a1, b1)), __fmul_rn(a2, b2));
}

// 256-bit zero store (Blackwell STG.E.256).
__device__ __forceinline__ void stg256_zero(float* p) {
    asm volatile(
        "st.global.v8.f32 [%0], {%1, %1, %1, %1, %1, %1, %1, %1};"
        :: "l"(p), "f"(0.0f) : "memory");
}

// Gauss-Jordan inverse with partial pivoting (fp32), matches jnp.linalg.inv LU path
// for these inputs. Op sequence frozen (bit-exactness validated R3..R14).
__device__ void inv3_gj(const float* A, float* out) {
    float M[3][6];
    #pragma unroll
    for (int r = 0; r < 3; r++) {
        #pragma unroll
        for (int c = 0; c < 3; c++) {
            M[r][c] = A[r * 3 + c];
            M[r][c + 3] = (r == c) ? 1.0f : 0.0f;
        }
    }
    for (int col = 0; col < 3; col++) {
        int p = col; float mx = fabsf(M[col][col]);
        for (int r = col + 1; r < 3; r++) {
            float v = fabsf(M[r][col]);
            if (v > mx) { mx = v; p = r; }
        }
        if (p != col) {
            for (int c = 0; c < 6; c++) { float t = M[col][c]; M[col][c] = M[p][c]; M[p][c] = t; }
        }
        float piv = M[col][col];
        for (int r = col + 1; r < 3; r++) {
            float f = __fdiv_rn(M[r][col], piv);
            for (int c = col; c < 6; c++) M[r][c] = __fadd_rn(M[r][c], -__fmul_rn(f, M[col][c]));
        }
    }
    for (int col = 2; col >= 0; col--) {
        for (int r = 0; r < col; r++) {
            float f = __fdiv_rn(M[r][col], M[col][col]);
            for (int c = col; c < 6; c++) M[r][c] = __fadd_rn(M[r][c], -__fmul_rn(f, M[col][c]));
        }
    }
    #pragma unroll
    for (int r = 0; r < 3; r++) {
        float piv = M[r][r];
        #pragma unroll
        for (int c = 0; c < 3; c++) out[r * 3 + c] = __fdiv_rn(M[r][c + 3], piv);
    }
}

// Fused prep: blocks [0, ZERO_BLOCKS) zero scratch with STG.256 (half the
// store wavefronts of the STG.128 sweep); block ZERO_BLOCKS = camera params.
__global__ void __launch_bounds__(256) prep_kernel(const float* __restrict__ rots,
                                                   const float* __restrict__ trans,
                                                   const float* __restrict__ intrins,
                                                   const float* __restrict__ post_rots,
                                                   const float* __restrict__ post_trans) {
    if (blockIdx.x < ZERO_BLOCKS) {
        // 1,280,000 v8-stores total = ZERO_BLOCKS * 256 threads * 4 each (exact)
        size_t base = (size_t)blockIdx.x * 1024 + threadIdx.x;
        #pragma unroll
        for (int k = 0; k < 4; k++) {
            size_t idx = base + (size_t)k * 256;      // v8 index, always in range
            stg256_zero(g_scratch + idx * 8);
        }
        return;
    }
    int tid = threadIdx.x;
    if (tid < B_ * N_) {
        int i = tid;
        const float* R = rots    + i * 9;
        const float* K = intrins + i * 9;
        float Kinv[9];
        inv3_gj(K, Kinv);
        float* p = g_par + i * 24;
        #pragma unroll
        for (int r = 0; r < 3; r++)
            #pragma unroll
            for (int c = 0; c < 3; c++)
                p[9 + r * 3 + c] = dot3_nofma(R[r * 3 + 0], Kinv[0 * 3 + c],
                                              R[r * 3 + 1], Kinv[1 * 3 + c],
                                              R[r * 3 + 2], Kinv[2 * 3 + c]);
    } else if (tid < 2 * B_ * N_) {
        int i = tid - B_ * N_;
        const float* PR = post_rots + i * 9;
        float Pinv[9];
        inv3_gj(PR, Pinv);
        float* p = g_par + i * 24;
        #pragma unroll
        for (int k = 0; k < 9; k++) p[k] = Pinv[k];
        #pragma unroll
        for (int k = 0; k < 3; k++) p[18 + k] = post_trans[i * 3 + k];
        #pragma unroll
        for (int k = 0; k < 3; k++) p[21 + k] = trans[i * 3 + k];
    }
}

// Splat (FROZEN, committed-best): 4 points per warp (8 lanes per point),
// 2 float4 quads per lane, warp-uniform row decode. Plain launch, no PDL.
__global__ void __launch_bounds__(256) splat_kernel(const float* __restrict__ x) {
    int lane = threadIdx.x & 31;
    int warp_in_grid = (blockIdx.x * blockDim.x + threadIdx.x) >> 5;
    int pt  = lane >> 3;        // which of the warp's 4 points (w offset)
    int cg  = lane & 7;         // quad-pair index: quads cg and cg+8

    // warp-uniform decode: warp -> (row, chunk); row -> (b, n, d, h)
    int chunk = warp_in_grid % (FW_ / 4);          // [0,11)
    int row   = warp_in_grid / (FW_ / 4);          // [0, B*N*D*FH)
    int h  = row % FH_;   int r2 = row / FH_;
    int dd = r2 % D_;     int r3 = r2 / D_;
    int n  = r3 % N_;
    int b  = r3 / N_;

    int w   = chunk * 4 + pt;                      // per-lane: uniform + pt
    int pid = row * FW_ + w;

    const float* par = g_par + (b * N_ + n) * 24;

    float fx = __fmul_rn((float)w, XSTEP);
    float fy = __fmul_rn((float)h, YSTEP);
    float fd = 4.0f + (float)dd;   // exact integers

    float px = __fadd_rn(fx, -__ldg(&par[18]));
    float py = __fadd_rn(fy, -__ldg(&par[19]));
    float pz = __fadd_rn(fd, -__ldg(&par[20]));

    float qx = dot3_nofma(__ldg(&par[0]), px, __ldg(&par[1]), py, __ldg(&par[2]), pz);
    float qy = dot3_nofma(__ldg(&par[3]), px, __ldg(&par[4]), py, __ldg(&par[5]), pz);
    float qz = dot3_nofma(__ldg(&par[6]), px, __ldg(&par[7]), py, __ldg(&par[8]), pz);

    float rx = __fmul_rn(qx, qz), ry = __fmul_rn(qy, qz), rz = qz;

    float gx = __fadd_rn(dot3_nofma(__ldg(&par[9]),  rx, __ldg(&par[10]), ry, __ldg(&par[11]), rz), __ldg(&par[21]));
    float gy = __fadd_rn(dot3_nofma(__ldg(&par[12]), rx, __ldg(&par[13]), ry, __ldg(&par[14]), rz), __ldg(&par[22]));
    float gz = __fadd_rn(dot3_nofma(__ldg(&par[15]), rx, __ldg(&par[16]), ry, __ldg(&par[17]), rz), __ldg(&par[23]));

    // (g+50)/0.5 == (g+50)*2 bit-exactly (division by a power of two; validated R6..R14)
    float vx = __fmul_rn(__fadd_rn(gx, 50.0f), 2.0f);
    float vy = __fmul_rn(__fadd_rn(gy, 50.0f), 2.0f);
    float vz = __fdiv_rn(__fadd_rn(gz, 10.0f), 20.0f);
    vx = fminf(fmaxf(vx, -1e6f), 1e6f);
    vy = fminf(fmaxf(vy, -1e6f), 1e6f);
    vz = fminf(fmaxf(vz, -1e6f), 1e6f);
    int ix = (int)vx;   // trunc toward zero
    int iy = (int)vy;
    int iz = (int)vz;

    bool kept = (ix >= 0) && (ix < NX0_) && (iy >= 0) && (iy < NX1_) && (iz == 0);
    if (!kept) return;

    const float4* src = reinterpret_cast<const float4*>(x + (size_t)pid * C_);
    float4 v0 = __ldg(src + cg);
    float4 v1 = __ldg(src + cg + 8);

    float* dst = &g_scratch[(((size_t)b * NX0_ + ix) * NX1_ + iy) * C_];
    atomicAdd(reinterpret_cast<float4*>(dst + cg * 4), v0);
    atomicAdd(reinterpret_cast<float4*>(dst + cg * 4 + 32), v1);
}

// Transpose [B, X, Y, C] -> [B, C, X, Y]. Each block handles FOUR tiles
// (x = xa + k*50), 8y x 64c each, all-float4, MLP 4 per thread.
__global__ void __launch_bounds__(128) transpose_kernel(float* __restrict__ out) {
    __shared__ float tile[4][8][68];   // pad 68: 16B-aligned v4 slots
    int y0 = blockIdx.x * 8;
    int xa = blockIdx.y;               // [0,50)
    int b  = blockIdx.z;
    int tid = threadIdx.x;

    int cq = tid & 15;
    int yy = tid >> 4;
    #pragma unroll
    for (int k = 0; k < 4; k++) {
        int xx = xa + k * (NX0_ / 4);
        const float* src = g_scratch + (((size_t)b * NX0_ + xx) * NX1_ + y0) * C_;
        float4 v = *(reinterpret_cast<const float4*>(src + yy * C_) + cq);
        *reinterpret_cast<float4*>(&tile[k][yy][cq * 4]) = v;
    }
    __syncthreads();

    int c  = tid & 63;
    int yq = tid >> 6;
    #pragma unroll
    for (int k = 0; k < 4; k++) {
        int xx = xa + k * (NX0_ / 4);
        float4 o;
        o.x = tile[k][yq * 4 + 0][c];
        o.y = tile[k][yq * 4 + 1][c];
        o.z = tile[k][yq * 4 + 2][c];
        o.w = tile[k][yq * 4 + 3][c];
        *reinterpret_cast<float4*>(out + (((size_t)(b * C_ + c)) * NX0_ + xx) * NX1_ + y0 + yq * 4) = o;
    }
}

extern "C" void kernel_launch(void* const* d_in, const int* in_sizes, int n_in,
                              void* d_out, int out_size) {
    const float* x          = (const float*)d_in[0];
    const float* rots       = (const float*)d_in[1];
    const float* trans      = (const float*)d_in[2];
    const float* intrins    = (const float*)d_in[3];
    const float* post_rots  = (const float*)d_in[4];
    const float* post_trans = (const float*)d_in[5];
    float* out = (float*)d_out;

    // fused zero (L2-warming STG.256 sweep) + camera params
    prep_kernel<<<ZERO_BLOCKS + 1, 256>>>(rots, trans, intrins, post_rots, post_trans);

    {
        // 4 points per warp, 8 warps per block -> 32 points per block
        int blocks = NPTS / 32;   // 21648, exact
        splat_kernel<<<blocks, 256>>>(x);
    }

    {
        dim3 grid(NX1_ / 8, NX0_ / 4, B_);  // (25, 50, 4)
        transpose_kernel<<<grid, 128>>>(out);
    }
}